// round 8
// baseline (speedup 1.0000x reference)
#include <cuda_runtime.h>
#include <cuda_bf16.h>
#include <cstdint>

// Problem constants
#define BB   8
#define LL   1024
#define KNB  30
#define NUM_RBF 16
#define NPOS 16
#define MAXREL 32
#define EDGE 128
#define EDGE_IN (NPOS + NUM_RBF * 25)   // 416 = 26 * 16
#define NEDGE (BB * LL * KNB)           // 245760
#define E_ELEMS ((size_t)NEDGE * EDGE)  // 31457280
#define NKSTEP 26
#define KCHUNK 13                       // ksteps per B chunk

__constant__ int cPI[25] = {0,1,2,3,4,0,0,0,0,1,1,1,4,4,3,1,2,3,4,2,3,4,2,3,2};
__constant__ int cPJ[25] = {0,1,2,3,4,1,2,3,4,2,3,4,2,3,2,0,0,0,0,1,1,1,4,4,3};

// Scratch (static __device__ — no allocations allowed)
__device__ float4 g_atoms[BB * LL * 5];   // [Ca, N, C, O, Cb] per residue
__device__ float4 g_ca[BB * LL];
__device__ int    g_eidx[NEDGE];
// W_edge^T split: [split(hi,lo)][n=128][k=416] bf16  (row = 832 B = 52 uint4)
__device__ __align__(16) __nv_bfloat16 g_Bt[2 * 128 * 416];

// ---------------------------------------------------------------------------
// Small helpers
// ---------------------------------------------------------------------------
__device__ __forceinline__ uint32_t smem_u32(const void* p) {
    uint32_t a;
    asm("{ .reg .u64 t; cvta.to.shared.u64 t, %1; cvt.u32.u64 %0, t; }"
        : "=r"(a) : "l"(p));
    return a;
}
__device__ __forceinline__ uint32_t pack_bf16x2(float f0, float f1) {
    uint32_t r;
    asm("cvt.rn.bf16x2.f32 %0, %1, %2;" : "=r"(r) : "f"(f1), "f"(f0));
    return r;  // lo half = f0, hi half = f1
}
__device__ __forceinline__ void mma16816(float* d, const uint32_t* a,
                                         const uint32_t* b) {
    asm volatile(
        "mma.sync.aligned.m16n8k16.row.col.f32.bf16.bf16.f32 "
        "{%0,%1,%2,%3}, {%4,%5,%6,%7}, {%8,%9}, {%0,%1,%2,%3};"
        : "+f"(d[0]), "+f"(d[1]), "+f"(d[2]), "+f"(d[3])
        : "r"(a[0]), "r"(a[1]), "r"(a[2]), "r"(a[3]), "r"(b[0]), "r"(b[1]));
}
__device__ __forceinline__ void ldsm4(uint32_t* r, uint32_t addr) {
    asm volatile(
        "ldmatrix.sync.aligned.m8n8.x4.shared.b16 {%0,%1,%2,%3}, [%4];"
        : "=r"(r[0]), "=r"(r[1]), "=r"(r[2]), "=r"(r[3]) : "r"(addr));
}
__device__ __forceinline__ unsigned long long kmin64(unsigned long long a,
                                                     unsigned long long b) {
    return a < b ? a : b;
}

// ---------------------------------------------------------------------------
// Kernel A: build atom table (Cb from cross product)
// ---------------------------------------------------------------------------
__global__ void prep_kernel(const float* __restrict__ X) {
    int t = blockIdx.x * blockDim.x + threadIdx.x;
    if (t >= BB * LL) return;
    const float* x = X + (size_t)t * 12;
    float Nx = x[0], Ny = x[1], Nz = x[2];
    float Ax = x[3], Ay = x[4], Az = x[5];
    float Cx = x[6], Cy = x[7], Cz = x[8];
    float Ox = x[9], Oy = x[10], Oz = x[11];
    float bx = Ax - Nx, by = Ay - Ny, bz = Az - Nz;
    float cx = Cx - Ax, cy = Cy - Ay, cz = Cz - Az;
    float ax = by * cz - bz * cy;
    float ay = bz * cx - bx * cz;
    float az = bx * cy - by * cx;
    float Bx = -0.58273431f * ax + 0.56802827f * bx - 0.54067466f * cx + Ax;
    float By = -0.58273431f * ay + 0.56802827f * by - 0.54067466f * cy + Ay;
    float Bz = -0.58273431f * az + 0.56802827f * bz - 0.54067466f * cz + Az;
    g_atoms[t * 5 + 0] = make_float4(Ax, Ay, Az, 0.f);
    g_atoms[t * 5 + 1] = make_float4(Nx, Ny, Nz, 0.f);
    g_atoms[t * 5 + 2] = make_float4(Cx, Cy, Cz, 0.f);
    g_atoms[t * 5 + 3] = make_float4(Ox, Oy, Oz, 0.f);
    g_atoms[t * 5 + 4] = make_float4(Bx, By, Bz, 0.f);
    g_ca[t] = make_float4(Ax, Ay, Az, 0.f);
}

// ---------------------------------------------------------------------------
// Kernel A2: W_edge^T hi/lo bf16 split into g_Bt [2][128][416]
// ---------------------------------------------------------------------------
__global__ void bprep_kernel(const float* __restrict__ W_edge) {
    int idx = blockIdx.x * blockDim.x + threadIdx.x;  // 128*416 = 53248
    if (idx >= 128 * 416) return;
    int n = idx / 416;
    int k = idx - n * 416;
    float w = W_edge[k * 128 + n];
    __nv_bfloat16 hb = __float2bfloat16(w);
    float hf = __bfloat162float(hb);
    __nv_bfloat16 lb = __float2bfloat16(w - hf);
    g_Bt[(size_t)n * 416 + k] = hb;
    g_Bt[(size_t)(128 + n) * 416 + k] = lb;
}

// ---------------------------------------------------------------------------
// Kernel B: top-30 nearest neighbors per row (exact JAX tie-breaking).
// 32-bit keys (positive-float bit order) + per-lane index tracking; cross-
// lane reduce on packed (val<<32|j) to keep smallest-j tie-breaking.
// ---------------------------------------------------------------------------
__global__ void topk_kernel(float* __restrict__ idx_out_f, int write_idx_f) {
    __shared__ uint32_t keys[LL];
    int row = blockIdx.x;
    int lane = threadIdx.x;
    int b = row >> 10;
    int base = b * LL;
    float4 ci = g_ca[row];

    for (int j = lane; j < LL; j += 32) {
        float4 cj = g_ca[base + j];
        float dx = ci.x - cj.x, dy = ci.y - cj.y, dz = ci.z - cj.z;
        float dist = sqrtf(dx * dx + dy * dy + dz * dz + 1e-6f);
        keys[j] = __float_as_uint(dist);
    }
    __syncwarp();

    for (int kk = 0; kk < KNB; kk++) {
        uint32_t v0 = ~0u, v1 = ~0u, v2 = ~0u, v3 = ~0u;
        int j0 = 0, j1 = 0, j2 = 0, j3 = 0;
        #pragma unroll
        for (int j = 0; j < LL; j += 128) {
            uint32_t a0 = keys[j + lane];
            uint32_t a1 = keys[j + lane + 32];
            uint32_t a2 = keys[j + lane + 64];
            uint32_t a3 = keys[j + lane + 96];
            if (a0 < v0) { v0 = a0; j0 = j + lane; }
            if (a1 < v1) { v1 = a1; j1 = j + lane + 32; }
            if (a2 < v2) { v2 = a2; j2 = j + lane + 64; }
            if (a3 < v3) { v3 = a3; j3 = j + lane + 96; }
        }
        unsigned long long best =
            kmin64(kmin64(((unsigned long long)v0 << 32) | (unsigned)j0,
                          ((unsigned long long)v1 << 32) | (unsigned)j1),
                   kmin64(((unsigned long long)v2 << 32) | (unsigned)j2,
                          ((unsigned long long)v3 << 32) | (unsigned)j3));
        #pragma unroll
        for (int off = 16; off; off >>= 1)
            best = kmin64(best, __shfl_xor_sync(0xffffffffu, best, off));
        unsigned j = (unsigned)(best & 0xffffffffu);
        if (lane == 0) {
            g_eidx[row * KNB + kk] = (int)j;
            if (write_idx_f) idx_out_f[row * KNB + kk] = (float)j;
            keys[j] = ~0u;
        }
        __syncwarp();
    }
}

// ---------------------------------------------------------------------------
// Kernel C: HMMA (mma.sync bf16x3) edge GEMM + LayerNorm.
// CTA: 512 threads / 16 warps in a 4(M)x4(N) grid.
// Warp tile: M=32 (2 m16 tiles) x N=32 (4 n8 tiles). K=416 (26 ksteps).
// SMEM: Bs[2 split][128 n][432 B rows, 208 k bf16 chunk]      110592
//       As[2 buf][2 split][128 e][48 B rows, 16 k bf16]        24576
//       sdist[128][25] f32                                     12800 (reused for LN)
//       spos [128][16] f32                                      8192
// ---------------------------------------------------------------------------
#define SM_BS   0
#define SM_AS   110592
#define SM_DIST 135168
#define SM_POS  147968
#define SM_TOTAL 156160
#define BS_SPLIT 55296     // 128 * 432
#define AS_BUF   12288     // 2 splits * 128 * 48
#define AS_SPLIT 6144      // 128 * 48

__global__ __launch_bounds__(512, 1) void edge_hmma_kernel(
    const int* __restrict__ res_idx,
    const float* __restrict__ W_pos,
    const float* __restrict__ b_pos,
    const float* __restrict__ ln_gamma,
    const float* __restrict__ ln_beta,
    float* __restrict__ outE) {

    extern __shared__ __align__(16) char smem[];
    uint32_t sbase = smem_u32(smem);
    int tid = threadIdx.x;
    int wid = tid >> 5;
    int lane = tid & 31;
    int mw = wid >> 2;        // 0..3  -> M slice of 32
    int nw = wid & 3;         // 0..3  -> N slice of 32

    float* sdist = (float*)(smem + SM_DIST);
    float* spos  = (float*)(smem + SM_POS);

    // ---- load B chunk 0 (all threads) ----
    {
        const uint4* src = (const uint4*)g_Bt;
        #pragma unroll
        for (int it = 0; it < 13; it++) {
            int idx = tid + it * 512;          // 0..6655
            int split = idx / 3328;
            int rem = idx - split * 3328;
            int n = rem / 26;
            int col = rem - n * 26;
            uint4 v = src[(split * 128 + n) * 52 + col];
            *(uint4*)(smem + SM_BS + split * BS_SPLIT + n * 432 + col * 16) = v;
        }
    }

    // ---- per-edge setup (threads 0..127) ----
    if (tid < 128) {
        int e = blockIdx.x * 128 + tid;
        int row = e / KNB;
        int b = row >> 10;
        int j = g_eidx[e];
        float4 pa[5], pb[5];
        #pragma unroll
        for (int a = 0; a < 5; a++) {
            pa[a] = g_atoms[row * 5 + a];
            pb[a] = g_atoms[(b * LL + j) * 5 + a];
        }
        #pragma unroll
        for (int p = 0; p < 25; p++) {
            float4 u = pa[cPI[p]], v = pb[cPJ[p]];
            float dx = u.x - v.x, dy = u.y - v.y, dz = u.z - v.z;
            sdist[tid * 25 + p] = sqrtf(dx * dx + dy * dy + dz * dz + 1e-6f);
        }
        int off = res_idx[row] - res_idx[b * LL + j];
        int dpos = off + MAXREL;
        dpos = dpos < 0 ? 0 : (dpos > 2 * MAXREL ? 2 * MAXREL : dpos);
        #pragma unroll
        for (int t = 0; t < NPOS; t++)
            spos[tid * 16 + t] = W_pos[dpos * NPOS + t] + b_pos[t];
    }
    __syncthreads();

    // ---- prefill A stage buf0 with kstep 0 (pos features) ----
    int fe = tid & 127;
    int fg = tid >> 7;                      // 0..3, each owns 2 bf16x2 words
    uint32_t fdst0 = sbase + SM_AS + fe * 48 + fg * 8;
    {
        #pragma unroll
        for (int i = 0; i < 2; i++) {
            int m0 = (fg * 2 + i) * 2;
            float f0 = spos[fe * 16 + m0];
            float f1 = spos[fe * 16 + m0 + 1];
            uint32_t hi = pack_bf16x2(f0, f1);
            float l0 = f0 - __uint_as_float(hi << 16);
            float l1 = f1 - __uint_as_float(hi & 0xffff0000u);
            uint32_t lo = pack_bf16x2(l0, l1);
            *(uint32_t*)(smem + SM_AS + fe * 48 + fg * 8 + i * 4) = hi;
            *(uint32_t*)(smem + SM_AS + AS_SPLIT + fe * 48 + fg * 8 + i * 4) = lo;
        }
    }
    __syncthreads();

    // ---- fragment address bases ----
    // A: warp covers rows [mw*32, mw*32+32); tile t adds t*16 rows (t*768 B).
    uint32_t a_base = sbase + SM_AS +
        (uint32_t)(mw * 32 + (lane & 15)) * 48 + (uint32_t)(lane >> 4) * 16;
    // B: warp covers n rows [nw*32, nw*32+32); n16 group g adds g*16 rows.
    uint32_t b_base = sbase + SM_BS + (uint32_t)(nw * 32) * 432 +
        (uint32_t)((lane & 7) + ((lane >> 4) << 3)) * 432 +
        (uint32_t)((lane >> 3) & 1) * 16;

    float acc[32];   // [t(2)][nt(4)][4]
    #pragma unroll
    for (int i = 0; i < 32; i++) acc[i] = 0.f;

    // ---- main K loop ----
    #pragma unroll 1
    for (int ks = 0; ks < NKSTEP; ks++) {
        if (ks == KCHUNK) {
            // reload B with chunk 1 (prev iter ended with syncthreads)
            const uint4* src = (const uint4*)g_Bt;
            #pragma unroll
            for (int it = 0; it < 13; it++) {
                int idx = tid + it * 512;
                int split = idx / 3328;
                int rem = idx - split * 3328;
                int n = rem / 26;
                int col = rem - n * 26;
                uint4 v = src[(split * 128 + n) * 52 + 26 + col];
                *(uint4*)(smem + SM_BS + split * BS_SPLIT + n * 432 + col * 16) = v;
            }
            __syncthreads();
        }
        int buf = ks & 1;
        int kk = (ks < KCHUNK) ? ks : ks - KCHUNK;

        // load fragments: A 2 tiles x 2 splits, B 2 n16-groups x 2 splits
        uint32_t ah[8], al[8];
        uint32_t abuf = a_base + buf * AS_BUF;
        #pragma unroll
        for (int t = 0; t < 2; t++) {
            ldsm4(&ah[t * 4], abuf + t * 768);
            ldsm4(&al[t * 4], abuf + t * 768 + AS_SPLIT);
        }
        uint32_t bh[8], bl[8];
        uint32_t bks = b_base + (uint32_t)kk * 32;
        #pragma unroll
        for (int g = 0; g < 2; g++) {
            ldsm4(&bh[g * 4], bks + g * 16 * 432);
            ldsm4(&bl[g * 4], bks + g * 16 * 432 + BS_SPLIT);
        }

        // prefetch features for ks+1 into other buffer (RBF only; ks+1>=1)
        int ksn = ks + 1;
        if (ksn < NKSTEP) {
            float d = sdist[fe * 25 + (ksn - 1)];
            uint32_t fd = fdst0 + (ksn & 1) * AS_BUF;
            #pragma unroll
            for (int i = 0; i < 2; i++) {
                int m0 = (fg * 2 + i) * 2;
                float mu0 = 2.0f + (float)m0 * 1.33333337f;
                float x0 = (d - mu0) * 0.8f;
                float x1 = (d - mu0 - 1.33333337f) * 0.8f;
                float f0 = __expf(-x0 * x0);
                float f1 = __expf(-x1 * x1);
                uint32_t hi = pack_bf16x2(f0, f1);
                float l0 = f0 - __uint_as_float(hi << 16);
                float l1 = f1 - __uint_as_float(hi & 0xffff0000u);
                uint32_t lo = pack_bf16x2(l0, l1);
                asm volatile("st.shared.b32 [%0], %1;" :: "r"(fd + i * 4), "r"(hi) : "memory");
                asm volatile("st.shared.b32 [%0], %1;" :: "r"(fd + AS_SPLIT + i * 4), "r"(lo) : "memory");
            }
        }

        // 24 MMAs: AhBh + AhBl + AlBh over 2 mtiles x 4 n8 tiles
        #pragma unroll
        for (int t = 0; t < 2; t++) {
            #pragma unroll
            for (int nt = 0; nt < 4; nt++) {
                float* a4 = &acc[(t * 4 + nt) * 4];
                mma16816(a4, &ah[t * 4], &bh[nt * 2]);
                mma16816(a4, &ah[t * 4], &bl[nt * 2]);
                mma16816(a4, &al[t * 4], &bh[nt * 2]);
            }
        }
        __syncthreads();
    }

    // ---- LayerNorm epilogue (cross-warp over the 4 N-slices) ----
    float* red1 = (float*)(smem + SM_DIST);          // [128][4] sums
    float* red2 = (float*)(smem + SM_DIST + 2048);   // [128][4] sq-sums

    int rbase = mw * 32 + (lane >> 2);
    // pass 1: sums
    #pragma unroll
    for (int t = 0; t < 2; t++) {
        float s1 = 0.f, s2 = 0.f;
        #pragma unroll
        for (int nt = 0; nt < 4; nt++) {
            const float* a4 = &acc[(t * 4 + nt) * 4];
            s1 += a4[0] + a4[1];
            s2 += a4[2] + a4[3];
        }
        s1 += __shfl_xor_sync(0xffffffffu, s1, 1);
        s1 += __shfl_xor_sync(0xffffffffu, s1, 2);
        s2 += __shfl_xor_sync(0xffffffffu, s2, 1);
        s2 += __shfl_xor_sync(0xffffffffu, s2, 2);
        if ((lane & 3) == 0) {
            red1[(rbase + t * 16) * 4 + nw] = s1;
            red1[(rbase + t * 16 + 8) * 4 + nw] = s2;
        }
    }
    __syncthreads();

    float mean1[2], mean2[2];
    #pragma unroll
    for (int t = 0; t < 2; t++) {
        float4 p1 = ((const float4*)red1)[rbase + t * 16];
        float4 p2 = ((const float4*)red1)[rbase + t * 16 + 8];
        mean1[t] = (p1.x + p1.y + p1.z + p1.w) * (1.0f / 128.0f);
        mean2[t] = (p2.x + p2.y + p2.z + p2.w) * (1.0f / 128.0f);
    }
    // pass 2: squared deviations
    #pragma unroll
    for (int t = 0; t < 2; t++) {
        float q1 = 0.f, q2 = 0.f;
        #pragma unroll
        for (int nt = 0; nt < 4; nt++) {
            const float* a4 = &acc[(t * 4 + nt) * 4];
            float d0 = a4[0] - mean1[t], d1 = a4[1] - mean1[t];
            float d2 = a4[2] - mean2[t], d3 = a4[3] - mean2[t];
            q1 += d0 * d0 + d1 * d1;
            q2 += d2 * d2 + d3 * d3;
        }
        q1 += __shfl_xor_sync(0xffffffffu, q1, 1);
        q1 += __shfl_xor_sync(0xffffffffu, q1, 2);
        q2 += __shfl_xor_sync(0xffffffffu, q2, 1);
        q2 += __shfl_xor_sync(0xffffffffu, q2, 2);
        if ((lane & 3) == 0) {
            red2[(rbase + t * 16) * 4 + nw] = q1;
            red2[(rbase + t * 16 + 8) * 4 + nw] = q2;
        }
    }
    __syncthreads();

    int ncol = nw * 32 + (lane & 3) * 2;
    #pragma unroll
    for (int t = 0; t < 2; t++) {
        float4 p1 = ((const float4*)red2)[rbase + t * 16];
        float4 p2 = ((const float4*)red2)[rbase + t * 16 + 8];
        float inv1 = rsqrtf((p1.x + p1.y + p1.z + p1.w) * (1.0f / 128.0f) + 1e-5f);
        float inv2 = rsqrtf((p2.x + p2.y + p2.z + p2.w) * (1.0f / 128.0f) + 1e-5f);
        size_t edge1 = (size_t)blockIdx.x * 128 + rbase + t * 16;
        size_t edge2 = edge1 + 8;
        #pragma unroll
        for (int nt = 0; nt < 4; nt++) {
            const float* a4 = &acc[(t * 4 + nt) * 4];
            int n0 = ncol + nt * 8;
            float2 gg = *(const float2*)(ln_gamma + n0);
            float2 bb = *(const float2*)(ln_beta + n0);
            float2 o1, o2;
            o1.x = (a4[0] - mean1[t]) * inv1 * gg.x + bb.x;
            o1.y = (a4[1] - mean1[t]) * inv1 * gg.y + bb.y;
            o2.x = (a4[2] - mean2[t]) * inv2 * gg.x + bb.x;
            o2.y = (a4[3] - mean2[t]) * inv2 * gg.y + bb.y;
            *(float2*)(outE + edge1 * 128 + n0) = o1;
            *(float2*)(outE + edge2 * 128 + n0) = o2;
        }
    }
}

// ---------------------------------------------------------------------------
// Launch. Input order: 0:X 1:mask 2:residue_idx 3:S 4:SSE3 5:SSE8 6:W_pos
// 7:b_pos 8:W_edge 9:ln_gamma 10:ln_beta.
// Output: E (f32, B*L*K*128) then E_idx as f32 (B*L*K).
// ---------------------------------------------------------------------------
extern "C" void kernel_launch(void* const* d_in, const int* in_sizes, int n_in,
                              void* d_out, int out_size) {
    const float* X        = (const float*)d_in[0];
    const int*   res_idx  = (const int*)  d_in[2];
    const float* W_pos    = (const float*)d_in[6];
    const float* b_pos    = (const float*)d_in[7];
    const float* W_edge   = (const float*)d_in[8];
    const float* ln_gamma = (const float*)d_in[9];
    const float* ln_beta  = (const float*)d_in[10];

    float* outE = (float*)d_out;
    int write_idx = (size_t)out_size >= E_ELEMS + (size_t)NEDGE;
    float* idx_out_f = write_idx ? outE + E_ELEMS : nullptr;

    cudaFuncSetAttribute(edge_hmma_kernel,
                         cudaFuncAttributeMaxDynamicSharedMemorySize, SM_TOTAL);

    prep_kernel<<<(BB * LL + 255) / 256, 256>>>(X);
    bprep_kernel<<<(128 * 416 + 255) / 256, 256>>>(W_edge);
    topk_kernel<<<BB * LL, 32>>>(idx_out_f, write_idx);
    edge_hmma_kernel<<<NEDGE / 128, 512, SM_TOTAL>>>(
        res_idx, W_pos, b_pos, ln_gamma, ln_beta, outE);
}

// round 9
// speedup vs baseline: 1.1010x; 1.1010x over previous
#include <cuda_runtime.h>
#include <cuda_bf16.h>
#include <cstdint>

// Problem constants
#define BB   8
#define LL   1024
#define KNB  30
#define NUM_RBF 16
#define NPOS 16
#define MAXREL 32
#define EDGE 128
#define EDGE_IN (NPOS + NUM_RBF * 25)   // 416 = 26 * 16
#define NEDGE (BB * LL * KNB)           // 245760
#define E_ELEMS ((size_t)NEDGE * EDGE)  // 31457280
#define NKSTEP 26
#define KCHUNK 13                       // ksteps per B chunk

__constant__ int cPI[25] = {0,1,2,3,4,0,0,0,0,1,1,1,4,4,3,1,2,3,4,2,3,4,2,3,2};
__constant__ int cPJ[25] = {0,1,2,3,4,1,2,3,4,2,3,4,2,3,2,0,0,0,0,1,1,1,4,4,3};

// Scratch (static __device__ — no allocations allowed)
__device__ float4 g_atoms[BB * LL * 5];   // [Ca, N, C, O, Cb] per residue
__device__ float4 g_ca[BB * LL];
__device__ int    g_eidx[NEDGE];
// W_edge^T split: [split(hi,lo)][n=128][k=416] bf16  (row = 832 B = 52 uint4)
__device__ __align__(16) __nv_bfloat16 g_Bt[2 * 128 * 416];

// ---------------------------------------------------------------------------
// Small helpers
// ---------------------------------------------------------------------------
__device__ __forceinline__ uint32_t smem_u32(const void* p) {
    uint32_t a;
    asm("{ .reg .u64 t; cvta.to.shared.u64 t, %1; cvt.u32.u64 %0, t; }"
        : "=r"(a) : "l"(p));
    return a;
}
__device__ __forceinline__ uint32_t pack_bf16x2(float f0, float f1) {
    uint32_t r;
    asm("cvt.rn.bf16x2.f32 %0, %1, %2;" : "=r"(r) : "f"(f1), "f"(f0));
    return r;  // lo half = f0, hi half = f1
}
__device__ __forceinline__ void mma16816(float* d, const uint32_t* a,
                                         const uint32_t* b) {
    asm volatile(
        "mma.sync.aligned.m16n8k16.row.col.f32.bf16.bf16.f32 "
        "{%0,%1,%2,%3}, {%4,%5,%6,%7}, {%8,%9}, {%0,%1,%2,%3};"
        : "+f"(d[0]), "+f"(d[1]), "+f"(d[2]), "+f"(d[3])
        : "r"(a[0]), "r"(a[1]), "r"(a[2]), "r"(a[3]), "r"(b[0]), "r"(b[1]));
}
__device__ __forceinline__ void ldsm4(uint32_t* r, uint32_t addr) {
    asm volatile(
        "ldmatrix.sync.aligned.m8n8.x4.shared.b16 {%0,%1,%2,%3}, [%4];"
        : "=r"(r[0]), "=r"(r[1]), "=r"(r[2]), "=r"(r[3]) : "r"(addr));
}
__device__ __forceinline__ unsigned long long kmin64(unsigned long long a,
                                                     unsigned long long b) {
    return a < b ? a : b;
}

// ---------------------------------------------------------------------------
// Kernel A: build atom table (Cb from cross product)
// ---------------------------------------------------------------------------
__global__ void prep_kernel(const float* __restrict__ X) {
    int t = blockIdx.x * blockDim.x + threadIdx.x;
    if (t >= BB * LL) return;
    const float* x = X + (size_t)t * 12;
    float Nx = x[0], Ny = x[1], Nz = x[2];
    float Ax = x[3], Ay = x[4], Az = x[5];
    float Cx = x[6], Cy = x[7], Cz = x[8];
    float Ox = x[9], Oy = x[10], Oz = x[11];
    float bx = Ax - Nx, by = Ay - Ny, bz = Az - Nz;
    float cx = Cx - Ax, cy = Cy - Ay, cz = Cz - Az;
    float ax = by * cz - bz * cy;
    float ay = bz * cx - bx * cz;
    float az = bx * cy - by * cx;
    float Bx = -0.58273431f * ax + 0.56802827f * bx - 0.54067466f * cx + Ax;
    float By = -0.58273431f * ay + 0.56802827f * by - 0.54067466f * cy + Ay;
    float Bz = -0.58273431f * az + 0.56802827f * bz - 0.54067466f * cz + Az;
    g_atoms[t * 5 + 0] = make_float4(Ax, Ay, Az, 0.f);
    g_atoms[t * 5 + 1] = make_float4(Nx, Ny, Nz, 0.f);
    g_atoms[t * 5 + 2] = make_float4(Cx, Cy, Cz, 0.f);
    g_atoms[t * 5 + 3] = make_float4(Ox, Oy, Oz, 0.f);
    g_atoms[t * 5 + 4] = make_float4(Bx, By, Bz, 0.f);
    g_ca[t] = make_float4(Ax, Ay, Az, 0.f);
}

// ---------------------------------------------------------------------------
// Kernel A2: W_edge^T hi/lo bf16 split into g_Bt [2][128][416]
// ---------------------------------------------------------------------------
__global__ void bprep_kernel(const float* __restrict__ W_edge) {
    int idx = blockIdx.x * blockDim.x + threadIdx.x;  // 128*416 = 53248
    if (idx >= 128 * 416) return;
    int n = idx / 416;
    int k = idx - n * 416;
    float w = W_edge[k * 128 + n];
    __nv_bfloat16 hb = __float2bfloat16(w);
    float hf = __bfloat162float(hb);
    __nv_bfloat16 lb = __float2bfloat16(w - hf);
    g_Bt[(size_t)n * 416 + k] = hb;
    g_Bt[(size_t)(128 + n) * 416 + k] = lb;
}

// ---------------------------------------------------------------------------
// Kernel B: top-30 nearest neighbors per row (exact JAX tie-breaking).
// 32-bit keys (positive-float bit order) + per-lane index tracking; cross-
// lane reduce on packed (val<<32|j) to keep smallest-j tie-breaking.
// ---------------------------------------------------------------------------
__global__ void topk_kernel(float* __restrict__ idx_out_f, int write_idx_f) {
    __shared__ uint32_t keys[LL];
    int row = blockIdx.x;
    int lane = threadIdx.x;
    int b = row >> 10;
    int base = b * LL;
    float4 ci = g_ca[row];

    for (int j = lane; j < LL; j += 32) {
        float4 cj = g_ca[base + j];
        float dx = ci.x - cj.x, dy = ci.y - cj.y, dz = ci.z - cj.z;
        float dist = sqrtf(dx * dx + dy * dy + dz * dz + 1e-6f);
        keys[j] = __float_as_uint(dist);
    }
    __syncwarp();

    for (int kk = 0; kk < KNB; kk++) {
        uint32_t v0 = ~0u, v1 = ~0u, v2 = ~0u, v3 = ~0u;
        int j0 = 0, j1 = 0, j2 = 0, j3 = 0;
        #pragma unroll
        for (int j = 0; j < LL; j += 128) {
            uint32_t a0 = keys[j + lane];
            uint32_t a1 = keys[j + lane + 32];
            uint32_t a2 = keys[j + lane + 64];
            uint32_t a3 = keys[j + lane + 96];
            if (a0 < v0) { v0 = a0; j0 = j + lane; }
            if (a1 < v1) { v1 = a1; j1 = j + lane + 32; }
            if (a2 < v2) { v2 = a2; j2 = j + lane + 64; }
            if (a3 < v3) { v3 = a3; j3 = j + lane + 96; }
        }
        unsigned long long best =
            kmin64(kmin64(((unsigned long long)v0 << 32) | (unsigned)j0,
                          ((unsigned long long)v1 << 32) | (unsigned)j1),
                   kmin64(((unsigned long long)v2 << 32) | (unsigned)j2,
                          ((unsigned long long)v3 << 32) | (unsigned)j3));
        #pragma unroll
        for (int off = 16; off; off >>= 1)
            best = kmin64(best, __shfl_xor_sync(0xffffffffu, best, off));
        unsigned j = (unsigned)(best & 0xffffffffu);
        if (lane == 0) {
            g_eidx[row * KNB + kk] = (int)j;
            if (write_idx_f) idx_out_f[row * KNB + kk] = (float)j;
            keys[j] = ~0u;
        }
        __syncwarp();
    }
}

// ---------------------------------------------------------------------------
// Kernel C: HMMA (mma.sync bf16x3) edge GEMM + LayerNorm.
// CTA: 256 threads / 8 warps in a 4(M)x2(N) grid.
// Warp tile: M=32 (2 m16 tiles) x N=64 (8 n8 tiles). K=416 (26 ksteps).
// A fragments computed directly in registers (no staging, no per-k barrier).
// SMEM: Bs[2 split][128 n][432 B rows, 208 k bf16 chunk]      110592
//       sdist[128][25] f32 (reused for LN reductions)          12800
//       spos [128][16] f32                                      8192
// ---------------------------------------------------------------------------
#define SM_BS   0
#define SM_DIST 110592
#define SM_POS  123392
#define SM_TOTAL 131584
#define BS_SPLIT 55296     // 128 * 432

__global__ __launch_bounds__(256, 1) void edge_hmma_kernel(
    const int* __restrict__ res_idx,
    const float* __restrict__ W_pos,
    const float* __restrict__ b_pos,
    const float* __restrict__ ln_gamma,
    const float* __restrict__ ln_beta,
    float* __restrict__ outE) {

    extern __shared__ __align__(16) char smem[];
    uint32_t sbase = smem_u32(smem);
    int tid = threadIdx.x;
    int wid = tid >> 5;
    int lane = tid & 31;
    int mw = wid >> 1;        // 0..3  -> M slice of 32
    int nw = wid & 1;         // 0..1  -> N slice of 64

    float* sdist = (float*)(smem + SM_DIST);
    float* spos  = (float*)(smem + SM_POS);

    // ---- load B chunk 0 (all threads) ----
    {
        const uint4* src = (const uint4*)g_Bt;
        #pragma unroll
        for (int it = 0; it < 26; it++) {
            int idx = tid + it * 256;          // 0..6655
            int split = idx / 3328;
            int rem = idx - split * 3328;
            int n = rem / 26;
            int col = rem - n * 26;
            uint4 v = src[(split * 128 + n) * 52 + col];
            *(uint4*)(smem + SM_BS + split * BS_SPLIT + n * 432 + col * 16) = v;
        }
    }

    // ---- per-edge setup (threads 0..127) ----
    if (tid < 128) {
        int e = blockIdx.x * 128 + tid;
        int row = e / KNB;
        int b = row >> 10;
        int j = g_eidx[e];
        float4 pa[5], pb[5];
        #pragma unroll
        for (int a = 0; a < 5; a++) {
            pa[a] = g_atoms[row * 5 + a];
            pb[a] = g_atoms[(b * LL + j) * 5 + a];
        }
        #pragma unroll
        for (int p = 0; p < 25; p++) {
            float4 u = pa[cPI[p]], v = pb[cPJ[p]];
            float dx = u.x - v.x, dy = u.y - v.y, dz = u.z - v.z;
            sdist[tid * 25 + p] = sqrtf(dx * dx + dy * dy + dz * dz + 1e-6f);
        }
        int off = res_idx[row] - res_idx[b * LL + j];
        int dpos = off + MAXREL;
        dpos = dpos < 0 ? 0 : (dpos > 2 * MAXREL ? 2 * MAXREL : dpos);
        #pragma unroll
        for (int t = 0; t < NPOS; t++)
            spos[tid * 16 + t] = W_pos[dpos * NPOS + t] + b_pos[t];
    }
    __syncthreads();

    // ---- per-lane constants for A-fragment feature generation ----
    int rq = lane >> 2;                    // 0..7
    int rbase = mw * 32 + rq;              // local edge row for t=0
    int cq = (lane & 3) * 2;               // k-col within kstep
    // x = 0.8*d - 0.8*mu ; hoist 0.8*mu for the 4 cols this lane owns
    float muA = 2.0f + (float)cq * 1.33333337f;
    float m0 = muA * 0.8f;
    float m1 = (muA + 1.33333337f) * 0.8f;
    float m8 = (muA + 8.0f * 1.33333337f) * 0.8f;
    float m9 = (muA + 9.0f * 1.33333337f) * 0.8f;

    // B fragment base: warp covers n rows [nw*64, nw*64+64)
    uint32_t b_base = sbase + SM_BS + (uint32_t)(nw * 64) * 432 +
        (uint32_t)((lane & 7) + ((lane >> 4) << 3)) * 432 +
        (uint32_t)((lane >> 3) & 1) * 16;

    float acc[64];   // [t(2)][nt(8)][4]
    #pragma unroll
    for (int i = 0; i < 64; i++) acc[i] = 0.f;

    // ---- main K loop (no per-kstep barrier) ----
    #pragma unroll 1
    for (int ks = 0; ks < NKSTEP; ks++) {
        if (ks == KCHUNK) {
            __syncthreads();   // all warps done reading chunk 0
            const uint4* src = (const uint4*)g_Bt;
            #pragma unroll
            for (int it = 0; it < 26; it++) {
                int idx = tid + it * 256;
                int split = idx / 3328;
                int rem = idx - split * 3328;
                int n = rem / 26;
                int col = rem - n * 26;
                uint4 v = src[(split * 128 + n) * 52 + 26 + col];
                *(uint4*)(smem + SM_BS + split * BS_SPLIT + n * 432 + col * 16) = v;
            }
            __syncthreads();
        }
        int kk = (ks < KCHUNK) ? ks : ks - KCHUNK;

        // B fragments: 4 n16 groups x 2 splits
        uint32_t bh[16], bl[16];
        uint32_t bks = b_base + (uint32_t)kk * 32;
        #pragma unroll
        for (int g = 0; g < 4; g++) {
            ldsm4(&bh[g * 4], bks + g * 16 * 432);
            ldsm4(&bl[g * 4], bks + g * 16 * 432 + BS_SPLIT);
        }

        // A fragments in registers: 2 mtiles x (4 hi + 4 lo bf16x2)
        uint32_t ah[2][4], al[2][4];
        #pragma unroll
        for (int t = 0; t < 2; t++) {
            int eA = rbase + t * 16;
            int eB = eA + 8;
            float f0, f1, f2, f3, f4, f5, f6, f7;
            if (ks == 0) {
                f0 = spos[eA * 16 + cq];     f1 = spos[eA * 16 + cq + 1];
                f2 = spos[eB * 16 + cq];     f3 = spos[eB * 16 + cq + 1];
                f4 = spos[eA * 16 + cq + 8]; f5 = spos[eA * 16 + cq + 9];
                f6 = spos[eB * 16 + cq + 8]; f7 = spos[eB * 16 + cq + 9];
            } else {
                float dA = sdist[eA * 25 + ks - 1] * 0.8f;
                float dB = sdist[eB * 25 + ks - 1] * 0.8f;
                float x;
                x = dA - m0; f0 = __expf(-x * x);
                x = dA - m1; f1 = __expf(-x * x);
                x = dB - m0; f2 = __expf(-x * x);
                x = dB - m1; f3 = __expf(-x * x);
                x = dA - m8; f4 = __expf(-x * x);
                x = dA - m9; f5 = __expf(-x * x);
                x = dB - m8; f6 = __expf(-x * x);
                x = dB - m9; f7 = __expf(-x * x);
            }
            uint32_t h;
            h = pack_bf16x2(f0, f1); ah[t][0] = h;
            al[t][0] = pack_bf16x2(f0 - __uint_as_float(h << 16),
                                   f1 - __uint_as_float(h & 0xffff0000u));
            h = pack_bf16x2(f2, f3); ah[t][1] = h;
            al[t][1] = pack_bf16x2(f2 - __uint_as_float(h << 16),
                                   f3 - __uint_as_float(h & 0xffff0000u));
            h = pack_bf16x2(f4, f5); ah[t][2] = h;
            al[t][2] = pack_bf16x2(f4 - __uint_as_float(h << 16),
                                   f5 - __uint_as_float(h & 0xffff0000u));
            h = pack_bf16x2(f6, f7); ah[t][3] = h;
            al[t][3] = pack_bf16x2(f6 - __uint_as_float(h << 16),
                                   f7 - __uint_as_float(h & 0xffff0000u));
        }

        // 48 MMAs: AhBh + AhBl + AlBh over 2 mtiles x 8 n8 tiles
        #pragma unroll
        for (int t = 0; t < 2; t++) {
            #pragma unroll
            for (int nt = 0; nt < 8; nt++) {
                float* a4 = &acc[(t * 8 + nt) * 4];
                const uint32_t* bhp = &bh[(nt >> 1) * 4 + (nt & 1) * 2];
                const uint32_t* blp = &bl[(nt >> 1) * 4 + (nt & 1) * 2];
                mma16816(a4, ah[t], bhp);
                mma16816(a4, ah[t], blp);
                mma16816(a4, al[t], bhp);
            }
        }
    }

    // ---- LayerNorm epilogue (cross-warp over the 2 N-slices) ----
    __syncthreads();   // protect sdist reuse
    float* red1 = (float*)(smem + SM_DIST);          // [128][2] sums
    float* red2 = (float*)(smem + SM_DIST + 1024);   // [128][2] sq-sums

    // pass 1: sums
    #pragma unroll
    for (int t = 0; t < 2; t++) {
        float s1 = 0.f, s2 = 0.f;
        #pragma unroll
        for (int nt = 0; nt < 8; nt++) {
            const float* a4 = &acc[(t * 8 + nt) * 4];
            s1 += a4[0] + a4[1];
            s2 += a4[2] + a4[3];
        }
        s1 += __shfl_xor_sync(0xffffffffu, s1, 1);
        s1 += __shfl_xor_sync(0xffffffffu, s1, 2);
        s2 += __shfl_xor_sync(0xffffffffu, s2, 1);
        s2 += __shfl_xor_sync(0xffffffffu, s2, 2);
        if ((lane & 3) == 0) {
            red1[(rbase + t * 16) * 2 + nw] = s1;
            red1[(rbase + t * 16 + 8) * 2 + nw] = s2;
        }
    }
    __syncthreads();

    float mean1[2], mean2[2];
    #pragma unroll
    for (int t = 0; t < 2; t++) {
        float2 p1 = ((const float2*)red1)[rbase + t * 16];
        float2 p2 = ((const float2*)red1)[rbase + t * 16 + 8];
        mean1[t] = (p1.x + p1.y) * (1.0f / 128.0f);
        mean2[t] = (p2.x + p2.y) * (1.0f / 128.0f);
    }
    // pass 2: squared deviations
    #pragma unroll
    for (int t = 0; t < 2; t++) {
        float q1 = 0.f, q2 = 0.f;
        #pragma unroll
        for (int nt = 0; nt < 8; nt++) {
            const float* a4 = &acc[(t * 8 + nt) * 4];
            float d0 = a4[0] - mean1[t], d1 = a4[1] - mean1[t];
            float d2 = a4[2] - mean2[t], d3 = a4[3] - mean2[t];
            q1 += d0 * d0 + d1 * d1;
            q2 += d2 * d2 + d3 * d3;
        }
        q1 += __shfl_xor_sync(0xffffffffu, q1, 1);
        q1 += __shfl_xor_sync(0xffffffffu, q1, 2);
        q2 += __shfl_xor_sync(0xffffffffu, q2, 1);
        q2 += __shfl_xor_sync(0xffffffffu, q2, 2);
        if ((lane & 3) == 0) {
            red2[(rbase + t * 16) * 2 + nw] = q1;
            red2[(rbase + t * 16 + 8) * 2 + nw] = q2;
        }
    }
    __syncthreads();

    int ncol = nw * 64 + cq;
    #pragma unroll
    for (int t = 0; t < 2; t++) {
        float2 p1 = ((const float2*)red2)[rbase + t * 16];
        float2 p2 = ((const float2*)red2)[rbase + t * 16 + 8];
        float inv1 = rsqrtf((p1.x + p1.y) * (1.0f / 128.0f) + 1e-5f);
        float inv2 = rsqrtf((p2.x + p2.y) * (1.0f / 128.0f) + 1e-5f);
        size_t edge1 = (size_t)blockIdx.x * 128 + rbase + t * 16;
        size_t edge2 = edge1 + 8;
        #pragma unroll
        for (int nt = 0; nt < 8; nt++) {
            const float* a4 = &acc[(t * 8 + nt) * 4];
            int n0 = ncol + nt * 8;
            float2 gg = *(const float2*)(ln_gamma + n0);
            float2 bb = *(const float2*)(ln_beta + n0);
            float2 o1, o2;
            o1.x = (a4[0] - mean1[t]) * inv1 * gg.x + bb.x;
            o1.y = (a4[1] - mean1[t]) * inv1 * gg.y + bb.y;
            o2.x = (a4[2] - mean2[t]) * inv2 * gg.x + bb.x;
            o2.y = (a4[3] - mean2[t]) * inv2 * gg.y + bb.y;
            *(float2*)(outE + edge1 * 128 + n0) = o1;
            *(float2*)(outE + edge2 * 128 + n0) = o2;
        }
    }
}

// ---------------------------------------------------------------------------
// Launch. Input order: 0:X 1:mask 2:residue_idx 3:S 4:SSE3 5:SSE8 6:W_pos
// 7:b_pos 8:W_edge 9:ln_gamma 10:ln_beta.
// Output: E (f32, B*L*K*128) then E_idx as f32 (B*L*K).
// ---------------------------------------------------------------------------
extern "C" void kernel_launch(void* const* d_in, const int* in_sizes, int n_in,
                              void* d_out, int out_size) {
    const float* X        = (const float*)d_in[0];
    const int*   res_idx  = (const int*)  d_in[2];
    const float* W_pos    = (const float*)d_in[6];
    const float* b_pos    = (const float*)d_in[7];
    const float* W_edge   = (const float*)d_in[8];
    const float* ln_gamma = (const float*)d_in[9];
    const float* ln_beta  = (const float*)d_in[10];

    float* outE = (float*)d_out;
    int write_idx = (size_t)out_size >= E_ELEMS + (size_t)NEDGE;
    float* idx_out_f = write_idx ? outE + E_ELEMS : nullptr;

    cudaFuncSetAttribute(edge_hmma_kernel,
                         cudaFuncAttributeMaxDynamicSharedMemorySize, SM_TOTAL);

    prep_kernel<<<(BB * LL + 255) / 256, 256>>>(X);
    bprep_kernel<<<(128 * 416 + 255) / 256, 256>>>(W_edge);
    topk_kernel<<<BB * LL, 32>>>(idx_out_f, write_idx);
    edge_hmma_kernel<<<NEDGE / 128, 256, SM_TOTAL>>>(
        res_idx, W_pos, b_pos, ln_gamma, ln_beta, outE);
}